// round 10
// baseline (speedup 1.0000x reference)
#include <cuda_runtime.h>
#include <cuda_fp16.h>
#include <cstdint>
#include <cstddef>

// ---------------------------------------------------------------------------
// Bidirectional GRU, B=4096 T=16 I=H=1024.
//   Gx = X @ [W_izr; W_it]^T   (one big GEMM, shared by both directions)
//   steps: one launch per (direction, step) = GEMM h@Wh^T for dir d PLUS a
//   tail that runs the gate elementwise work of the OTHER direction's
//   previous GEMM — hiding the memory-bound gate under tensor-bound GEMM.
// GEMM: fp16 in/out (fp32 accum), mma.sync.m16n8k16 + ldmatrix.x4 + cp.async,
// 128x128 CTA tile, 4 warps (64x64), BK=64, 3 stages, 2 CTAs/SM.
// Gate reads prev fp32 h from `out` (written by the prior gate).
// ---------------------------------------------------------------------------

namespace {
constexpr int B_ = 4096, T_ = 16, H_ = 1024;
constexpr int N3 = 3 * H_, K_ = 1024;
constexpr int BM = 128, BN = 128, BK = 64;   // CTA tile; BK in halfs
constexpr int NKT = K_ / BK;                 // 16 k-iterations
constexpr int NST = 3;                       // cp.async stages
constexpr int ROWB = 144;                    // smem row pitch (128B data + 16B pad)
constexpr int A_BYTES = BM * ROWB;           // 18432
constexpr int STAGE = 2 * A_BYTES;           // 36864 (A + B)
constexpr int SMEM_BYTES = NST * STAGE;      // 110592
}

// scratch (static device allocations; no runtime alloc allowed)
__device__ __align__(256) __half g_gx16[(size_t)B_ * T_ * N3];  // x-projections (fp16)
__device__ __align__(256) __half g_gh16[(size_t)2 * B_ * N3];   // h-projections (fp16)
__device__ __align__(256) float  g_h0 [(size_t)2 * B_ * H_];    // fp32 initial h per dir
__device__ __align__(256) __half g_h16[(size_t)4 * B_ * H_];    // fp16 h ping-pong (GEMM A)
__device__ __align__(256) __half g_x16[(size_t)B_ * T_ * K_];   // fp16 x
__device__ __align__(256) __half g_wx16[(size_t)N3 * K_];       // [W_izr; W_it] fp16
__device__ __align__(256) __half g_wh16[(size_t)N3 * K_];       // [W_hzr; W_ht] fp16

// ------------------------------ PTX helpers --------------------------------
__device__ __forceinline__ uint32_t smem_u32(const void* p) {
    uint32_t a;
    asm("{.reg .u64 t; cvta.to.shared.u64 t, %1; cvt.u32.u64 %0, t;}" : "=r"(a) : "l"(p));
    return a;
}
__device__ __forceinline__ void cp16(uint32_t d, const void* s) {
    asm volatile("cp.async.cg.shared.global [%0], [%1], 16;" :: "r"(d), "l"(s));
}
__device__ __forceinline__ void cp_commit() { asm volatile("cp.async.commit_group;"); }
template <int N>
__device__ __forceinline__ void cp_wait() { asm volatile("cp.async.wait_group %0;" :: "n"(N)); }

__device__ __forceinline__ void ldsm4(uint32_t& r0, uint32_t& r1, uint32_t& r2, uint32_t& r3,
                                      uint32_t a) {
    asm volatile("ldmatrix.sync.aligned.m8n8.x4.shared.b16 {%0,%1,%2,%3}, [%4];"
                 : "=r"(r0), "=r"(r1), "=r"(r2), "=r"(r3) : "r"(a));
}
__device__ __forceinline__ void mma16816(float c[4], const uint32_t a[4], const uint32_t b[2]) {
    asm volatile(
        "mma.sync.aligned.m16n8k16.row.col.f32.f16.f16.f32 "
        "{%0,%1,%2,%3},{%4,%5,%6,%7},{%8,%9},{%0,%1,%2,%3};"
        : "+f"(c[0]), "+f"(c[1]), "+f"(c[2]), "+f"(c[3])
        : "r"(a[0]), "r"(a[1]), "r"(a[2]), "r"(a[3]), "r"(b[0]), "r"(b[1]));
}
__device__ __forceinline__ float sigmoidf_(float x) { return 1.f / (1.f + expf(-x)); }

// shared GRU gate body for one float4 group (b, j)
__device__ __forceinline__ void gate_elem(
    int b, int j, int d, int s, int time, int tout,
    const float* __restrict__ b_izr, const float* __restrict__ b_hzr,
    const float* __restrict__ b_it,  const float* __restrict__ b_ht,
    float* __restrict__ out)
{
    const __half* gx = g_gx16 + ((size_t)b * T_ + time) * N3;
    const __half* gh = g_gh16 + (size_t)d * B_ * N3 + (size_t)b * N3;

    float4 h;
    if (s == 0) {
        h = *(const float4*)(g_h0 + (size_t)d * B_ * H_ + (size_t)b * H_ + j);
    } else {
        const int tprev = (d == 0) ? (T_ - s) : (s - 1);
        h = *(const float4*)(out + ((size_t)b * T_ + tprev) * (2 * H_) +
                             (size_t)d * H_ + j);
    }
    const size_t hoff = ((size_t)d * 2 + ((s + 1) & 1)) * B_ * H_ + (size_t)b * H_ + j;

    uint2 uxr = *(const uint2*)(gx + j);
    uint2 uxz = *(const uint2*)(gx + H_ + j);
    uint2 uxt = *(const uint2*)(gx + 2 * H_ + j);
    uint2 uhr = *(const uint2*)(gh + j);
    uint2 uhz = *(const uint2*)(gh + H_ + j);
    uint2 uht = *(const uint2*)(gh + 2 * H_ + j);
    float4 bir = *(const float4*)(b_izr + j);
    float4 biz = *(const float4*)(b_izr + H_ + j);
    float4 bhr = *(const float4*)(b_hzr + j);
    float4 bhz = *(const float4*)(b_hzr + H_ + j);
    float4 bti = *(const float4*)(b_it + j);
    float4 bth = *(const float4*)(b_ht + j);

    float2 xr0 = __half22float2(*reinterpret_cast<__half2*>(&uxr.x));
    float2 xr1 = __half22float2(*reinterpret_cast<__half2*>(&uxr.y));
    float2 xz0 = __half22float2(*reinterpret_cast<__half2*>(&uxz.x));
    float2 xz1 = __half22float2(*reinterpret_cast<__half2*>(&uxz.y));
    float2 xt0 = __half22float2(*reinterpret_cast<__half2*>(&uxt.x));
    float2 xt1 = __half22float2(*reinterpret_cast<__half2*>(&uxt.y));
    float2 hr0 = __half22float2(*reinterpret_cast<__half2*>(&uhr.x));
    float2 hr1 = __half22float2(*reinterpret_cast<__half2*>(&uhr.y));
    float2 hz0 = __half22float2(*reinterpret_cast<__half2*>(&uhz.x));
    float2 hz1 = __half22float2(*reinterpret_cast<__half2*>(&uhz.y));
    float2 ht0 = __half22float2(*reinterpret_cast<__half2*>(&uht.x));
    float2 ht1 = __half22float2(*reinterpret_cast<__half2*>(&uht.y));

    float4 nh;
#define GATE(c, GXR, GHR, GXZ, GHZ, GXT, GHT)                               \
    {                                                                       \
        float rg = sigmoidf_(GXR + GHR + bir.c + bhr.c);                    \
        float zg = sigmoidf_(GXZ + GHZ + biz.c + bhz.c);                    \
        float ht = tanhf(GXT + bti.c + rg * (GHT + bth.c));                 \
        nh.c = zg * ht + (1.f - zg) * h.c;                                  \
    }
    GATE(x, xr0.x, hr0.x, xz0.x, hz0.x, xt0.x, ht0.x)
    GATE(y, xr0.y, hr0.y, xz0.y, hz0.y, xt0.y, ht0.y)
    GATE(z, xr1.x, hr1.x, xz1.x, hz1.x, xt1.x, ht1.x)
    GATE(w, xr1.y, hr1.y, xz1.y, hz1.y, xt1.y, ht1.y)
#undef GATE

    __half2 p0 = __floats2half2_rn(nh.x, nh.y);
    __half2 p1 = __floats2half2_rn(nh.z, nh.w);
    uint2 u; u.x = *reinterpret_cast<uint32_t*>(&p0); u.y = *reinterpret_cast<uint32_t*>(&p1);
    *reinterpret_cast<uint2*>(g_h16 + hoff) = u;
    *(float4*)(out + ((size_t)b * T_ + tout) * (2 * H_) + (size_t)d * H_ + j) = nh;
}

// ----------------------- Gx GEMM (R5 config, no tail) -----------------------
__global__ __launch_bounds__(128, 2)
void gemm_gx()
{
    extern __shared__ __align__(128) char smem[];
    const uint32_t sb = smem_u32(smem);
    const int tid = threadIdx.x, warp = tid >> 5, lane = tid & 31;
    const int n0 = blockIdx.x * BN, mb = blockIdx.y * BM;

    const __half* A = g_x16 + (size_t)mb * K_;
    const __half* W = g_wx16 + (size_t)n0 * K_;

    const int wm = (warp & 1) * 64, wn = (warp >> 1) * 64;
    const uint32_t aFrag = sb + (uint32_t)(wm + (lane & 15)) * ROWB + ((lane >> 4) & 1) * 16;
    const uint32_t bFrag = sb + A_BYTES +
        (uint32_t)(wn + ((lane >> 4) & 1) * 8 + (lane & 7)) * ROWB + ((lane >> 3) & 1) * 16;

    float acc[4][8][4];
#pragma unroll
    for (int a = 0; a < 4; ++a)
#pragma unroll
        for (int b = 0; b < 8; ++b)
#pragma unroll
            for (int c = 0; c < 4; ++c) acc[a][b][c] = 0.f;

#define FILL(S, KT)                                                           \
    {                                                                         \
        _Pragma("unroll")                                                     \
        for (int i = 0; i < 8; ++i) {                                         \
            int c = tid + 128 * i;                                            \
            int row = c >> 3, col = c & 7;                                    \
            uint32_t d = sb + (S) * STAGE + row * ROWB + col * 16;            \
            cp16(d, A + (size_t)row * K_ + (KT) * BK + col * 8);              \
            cp16(d + A_BYTES, W + (size_t)row * K_ + (KT) * BK + col * 8);    \
        }                                                                     \
    }
#pragma unroll
    for (int s = 0; s < NST - 1; ++s) { FILL(s, s); cp_commit(); }
    int st = 0;
    for (int kt = 0; kt < NKT; ++kt) {
        cp_wait<NST - 2>();
        __syncthreads();
        if (kt + NST - 1 < NKT) {
            int fs = st + 2; if (fs >= NST) fs -= NST;
            FILL(fs, kt + NST - 1);
        }
        cp_commit();
        const uint32_t aS = aFrag + st * STAGE;
        const uint32_t bS = bFrag + st * STAGE;
#pragma unroll
        for (int ks = 0; ks < 4; ++ks) {
            uint32_t af[4][4], bf[8][2];
#pragma unroll
            for (int mi = 0; mi < 4; ++mi)
                ldsm4(af[mi][0], af[mi][1], af[mi][2], af[mi][3],
                      aS + mi * 16 * ROWB + ks * 32);
#pragma unroll
            for (int nj = 0; nj < 4; ++nj)
                ldsm4(bf[2 * nj][0], bf[2 * nj][1], bf[2 * nj + 1][0], bf[2 * nj + 1][1],
                      bS + nj * 16 * ROWB + ks * 32);
#pragma unroll
            for (int mi = 0; mi < 4; ++mi)
#pragma unroll
                for (int ni = 0; ni < 8; ++ni)
                    mma16816(acc[mi][ni], af[mi], bf[ni]);
        }
        if (++st == NST) st = 0;
    }
#undef FILL

    __half* crow = g_gx16 + (size_t)(mb + wm + (lane >> 2)) * N3 + n0 + wn + (lane & 3) * 2;
#pragma unroll
    for (int mi = 0; mi < 4; ++mi) {
#pragma unroll
        for (int ni = 0; ni < 8; ++ni) {
            *reinterpret_cast<__half2*>(crow + (size_t)(mi * 16) * N3 + ni * 8) =
                __floats2half2_rn(acc[mi][ni][0], acc[mi][ni][1]);
            *reinterpret_cast<__half2*>(crow + (size_t)(mi * 16 + 8) * N3 + ni * 8) =
                __floats2half2_rn(acc[mi][ni][2], acc[mi][ni][3]);
        }
    }
}

// ------------- step kernel: GEMM(gemm_dir) + gate tail(gate_dir) ------------
__global__ __launch_bounds__(128, 2)
void gemm_step(int gemm_dir, int gemm_phase, int gate_dir, int gate_s,
               const float* __restrict__ b_izr, const float* __restrict__ b_hzr,
               const float* __restrict__ b_it,  const float* __restrict__ b_ht,
               float* __restrict__ out)
{
    extern __shared__ __align__(128) char smem[];
    const uint32_t sb = smem_u32(smem);
    const int tid = threadIdx.x, warp = tid >> 5, lane = tid & 31;
    const int n0 = blockIdx.x * BN, mb = blockIdx.y * BM;

    const __half* A = g_h16 + (size_t)((gemm_dir * 2 + gemm_phase) * B_ + mb) * K_;
    const __half* W = g_wh16 + (size_t)n0 * K_;
    __half* C = g_gh16 + (size_t)gemm_dir * B_ * N3;

    const int wm = (warp & 1) * 64, wn = (warp >> 1) * 64;
    const uint32_t aFrag = sb + (uint32_t)(wm + (lane & 15)) * ROWB + ((lane >> 4) & 1) * 16;
    const uint32_t bFrag = sb + A_BYTES +
        (uint32_t)(wn + ((lane >> 4) & 1) * 8 + (lane & 7)) * ROWB + ((lane >> 3) & 1) * 16;

    float acc[4][8][4];
#pragma unroll
    for (int a = 0; a < 4; ++a)
#pragma unroll
        for (int b = 0; b < 8; ++b)
#pragma unroll
            for (int c = 0; c < 4; ++c) acc[a][b][c] = 0.f;

#define FILL(S, KT)                                                           \
    {                                                                         \
        _Pragma("unroll")                                                     \
        for (int i = 0; i < 8; ++i) {                                         \
            int c = tid + 128 * i;                                            \
            int row = c >> 3, col = c & 7;                                    \
            uint32_t d = sb + (S) * STAGE + row * ROWB + col * 16;            \
            cp16(d, A + (size_t)row * K_ + (KT) * BK + col * 8);              \
            cp16(d + A_BYTES, W + (size_t)row * K_ + (KT) * BK + col * 8);    \
        }                                                                     \
    }
#pragma unroll
    for (int s = 0; s < NST - 1; ++s) { FILL(s, s); cp_commit(); }
    int st = 0;
    for (int kt = 0; kt < NKT; ++kt) {
        cp_wait<NST - 2>();
        __syncthreads();
        if (kt + NST - 1 < NKT) {
            int fs = st + 2; if (fs >= NST) fs -= NST;
            FILL(fs, kt + NST - 1);
        }
        cp_commit();
        const uint32_t aS = aFrag + st * STAGE;
        const uint32_t bS = bFrag + st * STAGE;
#pragma unroll
        for (int ks = 0; ks < 4; ++ks) {
            uint32_t af[4][4], bf[8][2];
#pragma unroll
            for (int mi = 0; mi < 4; ++mi)
                ldsm4(af[mi][0], af[mi][1], af[mi][2], af[mi][3],
                      aS + mi * 16 * ROWB + ks * 32);
#pragma unroll
            for (int nj = 0; nj < 4; ++nj)
                ldsm4(bf[2 * nj][0], bf[2 * nj][1], bf[2 * nj + 1][0], bf[2 * nj + 1][1],
                      bS + nj * 16 * ROWB + ks * 32);
#pragma unroll
            for (int mi = 0; mi < 4; ++mi)
#pragma unroll
                for (int ni = 0; ni < 8; ++ni)
                    mma16816(acc[mi][ni], af[mi], bf[ni]);
        }
        if (++st == NST) st = 0;
    }
#undef FILL

    __half* crow = C + (size_t)(mb + wm + (lane >> 2)) * N3 + n0 + wn + (lane & 3) * 2;
#pragma unroll
    for (int mi = 0; mi < 4; ++mi) {
#pragma unroll
        for (int ni = 0; ni < 8; ++ni) {
            *reinterpret_cast<__half2*>(crow + (size_t)(mi * 16) * N3 + ni * 8) =
                __floats2half2_rn(acc[mi][ni][0], acc[mi][ni][1]);
            *reinterpret_cast<__half2*>(crow + (size_t)(mi * 16 + 8) * N3 + ni * 8) =
                __floats2half2_rn(acc[mi][ni][2], acc[mi][ni][3]);
        }
    }

    // ---- gate tail: other direction's gate from the PREVIOUS launch's GEMM ----
    if (gate_s < 0) return;
    const int d = gate_dir, s = gate_s;
    const int time = (d == 0) ? s : (T_ - 1 - s);
    const int tout = (d == 0) ? (T_ - 1 - s) : s;
    const int cta = blockIdx.y * gridDim.x + blockIdx.x;         // 0..767
    const int nthr = gridDim.x * gridDim.y * 128;                // 98304
    const int total = B_ * H_ / 4;                               // 1048576
    for (int idx = cta * 128 + tid; idx < total; idx += nthr) {
        const int j4 = idx << 2;
        const int b = j4 >> 10;
        const int j = j4 & (H_ - 1);
        gate_elem(b, j, d, s, time, tout, b_izr, b_hzr, b_it, b_ht, out);
    }
}

// ------------------------ final standalone gate ------------------------
__global__ __launch_bounds__(256)
void gate_final(const float* __restrict__ b_izr, const float* __restrict__ b_hzr,
                const float* __restrict__ b_it,  const float* __restrict__ b_ht,
                float* __restrict__ out, int d, int s)
{
    const int idx = blockIdx.x * blockDim.x + threadIdx.x;
    const int j4  = idx << 2;
    const int b   = j4 >> 10;
    const int j   = j4 & (H_ - 1);
    const int time = (d == 0) ? s : (T_ - 1 - s);
    const int tout = (d == 0) ? (T_ - 1 - s) : s;
    gate_elem(b, j, d, s, time, tout, b_izr, b_hzr, b_it, b_ht, out);
}

// ------------------------------ small kernels ------------------------------
__global__ void cvt16(const float* __restrict__ s, __half* __restrict__ d, int n4)
{
    int i = blockIdx.x * blockDim.x + threadIdx.x;
    if (i < n4) {
        float4 v = reinterpret_cast<const float4*>(s)[i];
        __half2 p0 = __floats2half2_rn(v.x, v.y);
        __half2 p1 = __floats2half2_rn(v.z, v.w);
        uint2 u; u.x = *reinterpret_cast<uint32_t*>(&p0); u.y = *reinterpret_cast<uint32_t*>(&p1);
        reinterpret_cast<uint2*>(d)[i] = u;
    }
}

__global__ void init_h(const float* __restrict__ h0, const float* __restrict__ bih0)
{
    size_t i = (size_t)blockIdx.x * blockDim.x + threadIdx.x;
    if (i < (size_t)B_ * H_) {
        float a = h0[i], b = bih0[i];
        g_h0[i] = a;
        g_h0[(size_t)B_ * H_ + i] = b;
        g_h16[i] = __float2half_rn(a);                       // dir 0, phase 0
        g_h16[(size_t)2 * B_ * H_ + i] = __float2half_rn(b); // dir 1, phase 0
    }
}

// ------------------------------ host side ----------------------------------
extern "C" void kernel_launch(void* const* d_in, const int* in_sizes, int n_in,
                              void* d_out, int out_size)
{
    const float* x     = (const float*)d_in[0];
    const float* h0    = (const float*)d_in[1];
    const float* bih0  = (const float*)d_in[2];
    const float* W_izr = (const float*)d_in[3];
    const float* b_izr = (const float*)d_in[4];
    const float* W_hzr = (const float*)d_in[5];
    const float* b_hzr = (const float*)d_in[6];
    const float* W_it  = (const float*)d_in[7];
    const float* b_it  = (const float*)d_in[8];
    const float* W_ht  = (const float*)d_in[9];
    const float* b_ht  = (const float*)d_in[10];
    float* out = (float*)d_out;
    (void)in_sizes; (void)n_in; (void)out_size;

    void *p_x16 = nullptr, *p_wx = nullptr, *p_wh = nullptr;
    cudaGetSymbolAddress(&p_x16, g_x16);
    cudaGetSymbolAddress(&p_wx, g_wx16);
    cudaGetSymbolAddress(&p_wh, g_wh16);

    cudaFuncSetAttribute(gemm_gx,   cudaFuncAttributeMaxDynamicSharedMemorySize, SMEM_BYTES);
    cudaFuncSetAttribute(gemm_step, cudaFuncAttributeMaxDynamicSharedMemorySize, SMEM_BYTES);

    // fp16 conversions
    const int WN4 = 2 * H_ * K_ / 4, WN4b = H_ * K_ / 4, XN4 = B_ * T_ * K_ / 4;
    cvt16<<<(WN4 + 255) / 256, 256>>>(W_izr, (__half*)p_wx, WN4);
    cvt16<<<(WN4b + 255) / 256, 256>>>(W_it, (__half*)p_wx + (size_t)2 * H_ * K_, WN4b);
    cvt16<<<(WN4 + 255) / 256, 256>>>(W_hzr, (__half*)p_wh, WN4);
    cvt16<<<(WN4b + 255) / 256, 256>>>(W_ht, (__half*)p_wh + (size_t)2 * H_ * K_, WN4b);
    cvt16<<<(XN4 + 255) / 256, 256>>>(x, (__half*)p_x16, XN4);
    init_h<<<(B_ * H_ + 255) / 256, 256>>>(h0, bih0);

    // Gx = X @ [W_izr; W_it]^T over all (b, t)
    gemm_gx<<<dim3(N3 / BN, (B_ * T_) / BM, 1), 128, SMEM_BYTES>>>();

    // 32 interleaved direction-step launches; each hides the other dir's gate
    for (int k = 0; k < T_; ++k) {
        gemm_step<<<dim3(N3 / BN, B_ / BM, 1), 128, SMEM_BYTES>>>(
            0, k & 1, 1, k - 1, b_izr, b_hzr, b_it, b_ht, out);
        gemm_step<<<dim3(N3 / BN, B_ / BM, 1), 128, SMEM_BYTES>>>(
            1, k & 1, 0, k, b_izr, b_hzr, b_it, b_ht, out);
    }
    // last gate for direction 1, step T-1
    gate_final<<<(B_ * H_) / (256 * 4), 256>>>(b_izr, b_hzr, b_it, b_ht, out, 1, T_ - 1);
}

// round 11
// speedup vs baseline: 1.3220x; 1.3220x over previous
#include <cuda_runtime.h>
#include <cuda_fp16.h>
#include <cstdint>
#include <cstddef>

// ---------------------------------------------------------------------------
// Bidirectional GRU, B=4096 T=16 I=H=1024.
//   Gx = X @ [W_izr; W_it]^T   (one big GEMM, shared by both directions)
//   then TWO INDEPENDENT direction chains (GEMM -> gate -> GEMM -> ...) run
//   on two forked streams inside the captured graph, so each direction's
//   memory-bound gate overlaps the other direction's tensor-bound GEMM.
// Kernels identical to the proven R9 config: fp16 in/out (fp32 accum) GEMM,
// mma.sync.m16n8k16 + ldmatrix.x4 + cp.async, 128x128 tile, 4 warps (64x64),
// BK=64, 3 stages, 2 CTAs/SM. Gate reads prev fp32 h from `out`.
// ---------------------------------------------------------------------------

namespace {
constexpr int B_ = 4096, T_ = 16, H_ = 1024;
constexpr int N3 = 3 * H_, K_ = 1024;
constexpr int BM = 128, BN = 128, BK = 64;   // CTA tile; BK in halfs
constexpr int NKT = K_ / BK;                 // 16 k-iterations
constexpr int NST = 3;                       // cp.async stages
constexpr int ROWB = 144;                    // smem row pitch (128B data + 16B pad)
constexpr int A_BYTES = BM * ROWB;           // 18432
constexpr int STAGE = 2 * A_BYTES;           // 36864 (A + B)
constexpr int SMEM_BYTES = NST * STAGE;      // 110592
}

// scratch (static device allocations; no runtime alloc allowed)
__device__ __align__(256) __half g_gx16[(size_t)B_ * T_ * N3];  // x-projections (fp16)
__device__ __align__(256) __half g_gh16[(size_t)2 * B_ * N3];   // h-projections (fp16)
__device__ __align__(256) float  g_h0 [(size_t)2 * B_ * H_];    // fp32 initial h per dir
__device__ __align__(256) __half g_h16[(size_t)4 * B_ * H_];    // fp16 h ping-pong (GEMM A)
__device__ __align__(256) __half g_x16[(size_t)B_ * T_ * K_];   // fp16 x
__device__ __align__(256) __half g_wx16[(size_t)N3 * K_];       // [W_izr; W_it] fp16
__device__ __align__(256) __half g_wh16[(size_t)N3 * K_];       // [W_hzr; W_ht] fp16

// ------------------------------ PTX helpers --------------------------------
__device__ __forceinline__ uint32_t smem_u32(const void* p) {
    uint32_t a;
    asm("{.reg .u64 t; cvta.to.shared.u64 t, %1; cvt.u32.u64 %0, t;}" : "=r"(a) : "l"(p));
    return a;
}
__device__ __forceinline__ void cp16(uint32_t d, const void* s) {
    asm volatile("cp.async.cg.shared.global [%0], [%1], 16;" :: "r"(d), "l"(s));
}
__device__ __forceinline__ void cp_commit() { asm volatile("cp.async.commit_group;"); }
template <int N>
__device__ __forceinline__ void cp_wait() { asm volatile("cp.async.wait_group %0;" :: "n"(N)); }

__device__ __forceinline__ void ldsm4(uint32_t& r0, uint32_t& r1, uint32_t& r2, uint32_t& r3,
                                      uint32_t a) {
    asm volatile("ldmatrix.sync.aligned.m8n8.x4.shared.b16 {%0,%1,%2,%3}, [%4];"
                 : "=r"(r0), "=r"(r1), "=r"(r2), "=r"(r3) : "r"(a));
}
__device__ __forceinline__ void mma16816(float c[4], const uint32_t a[4], const uint32_t b[2]) {
    asm volatile(
        "mma.sync.aligned.m16n8k16.row.col.f32.f16.f16.f32 "
        "{%0,%1,%2,%3},{%4,%5,%6,%7},{%8,%9},{%0,%1,%2,%3};"
        : "+f"(c[0]), "+f"(c[1]), "+f"(c[2]), "+f"(c[3])
        : "r"(a[0]), "r"(a[1]), "r"(a[2]), "r"(a[3]), "r"(b[0]), "r"(b[1]));
}
__device__ __forceinline__ float sigmoidf_(float x) { return 1.f / (1.f + expf(-x)); }

// ------------------------------ GEMM kernel --------------------------------
// recur=0: A = g_x16 (rows mb..), C = g_gx16.
// recur=1: A = g_h16[(dir*2+phase)], C = g_gh16[dir].
__global__ __launch_bounds__(128, 2)
void gemm_f16(int dir, int phase, int recur)
{
    extern __shared__ __align__(128) char smem[];
    const uint32_t sb = smem_u32(smem);
    const int tid = threadIdx.x, warp = tid >> 5, lane = tid & 31;
    const int n0 = blockIdx.x * BN, mb = blockIdx.y * BM;

    const __half* A = recur ? g_h16 + (size_t)((dir * 2 + phase) * B_ + mb) * K_
                            : g_x16 + (size_t)mb * K_;
    const __half* W = (recur ? g_wh16 : g_wx16) + (size_t)n0 * K_;
    __half* C = recur ? g_gh16 + (size_t)dir * B_ * N3 : g_gx16;

    // warp tile: 64 x 64  (warp grid 2 x 2)
    const int wm = (warp & 1) * 64, wn = (warp >> 1) * 64;
    const uint32_t aFrag = sb + (uint32_t)(wm + (lane & 15)) * ROWB + ((lane >> 4) & 1) * 16;
    const uint32_t bFrag = sb + A_BYTES +
        (uint32_t)(wn + ((lane >> 4) & 1) * 8 + (lane & 7)) * ROWB + ((lane >> 3) & 1) * 16;

    float acc[4][8][4];
#pragma unroll
    for (int a = 0; a < 4; ++a)
#pragma unroll
        for (int b = 0; b < 8; ++b)
#pragma unroll
            for (int c = 0; c < 4; ++c) acc[a][b][c] = 0.f;

#define FILL(S, KT)                                                           \
    {                                                                         \
        _Pragma("unroll")                                                     \
        for (int i = 0; i < 8; ++i) {                                         \
            int c = tid + 128 * i;                                            \
            int row = c >> 3, col = c & 7;                                    \
            uint32_t d = sb + (S) * STAGE + row * ROWB + col * 16;            \
            cp16(d, A + (size_t)row * K_ + (KT) * BK + col * 8);              \
            cp16(d + A_BYTES, W + (size_t)row * K_ + (KT) * BK + col * 8);    \
        }                                                                     \
    }

#pragma unroll
    for (int s = 0; s < NST - 1; ++s) { FILL(s, s); cp_commit(); }

    int st = 0;
    for (int kt = 0; kt < NKT; ++kt) {
        cp_wait<NST - 2>();
        __syncthreads();
        if (kt + NST - 1 < NKT) {
            int fs = st + 2; if (fs >= NST) fs -= NST;
            FILL(fs, kt + NST - 1);
        }
        cp_commit();

        const uint32_t aS = aFrag + st * STAGE;
        const uint32_t bS = bFrag + st * STAGE;
#pragma unroll
        for (int ks = 0; ks < 4; ++ks) {
            uint32_t af[4][4], bf[8][2];
#pragma unroll
            for (int mi = 0; mi < 4; ++mi)
                ldsm4(af[mi][0], af[mi][1], af[mi][2], af[mi][3],
                      aS + mi * 16 * ROWB + ks * 32);
#pragma unroll
            for (int nj = 0; nj < 4; ++nj)
                ldsm4(bf[2 * nj][0], bf[2 * nj][1], bf[2 * nj + 1][0], bf[2 * nj + 1][1],
                      bS + nj * 16 * ROWB + ks * 32);
#pragma unroll
            for (int mi = 0; mi < 4; ++mi)
#pragma unroll
                for (int ni = 0; ni < 8; ++ni)
                    mma16816(acc[mi][ni], af[mi], bf[ni]);
        }
        if (++st == NST) st = 0;
    }
#undef FILL

    __half* crow = C + (size_t)(mb + wm + (lane >> 2)) * N3 + n0 + wn + (lane & 3) * 2;
#pragma unroll
    for (int mi = 0; mi < 4; ++mi) {
#pragma unroll
        for (int ni = 0; ni < 8; ++ni) {
            *reinterpret_cast<__half2*>(crow + (size_t)(mi * 16) * N3 + ni * 8) =
                __floats2half2_rn(acc[mi][ni][0], acc[mi][ni][1]);
            *reinterpret_cast<__half2*>(crow + (size_t)(mi * 16 + 8) * N3 + ni * 8) =
                __floats2half2_rn(acc[mi][ni][2], acc[mi][ni][3]);
        }
    }
}

// ------------------------------ gate kernel --------------------------------
__global__ __launch_bounds__(256)
void gate_kernel(const float* __restrict__ b_izr, const float* __restrict__ b_hzr,
                 const float* __restrict__ b_it,  const float* __restrict__ b_ht,
                 float* __restrict__ out, int d, int s)
{
    const int idx = blockIdx.x * blockDim.x + threadIdx.x;
    const int j4  = idx << 2;
    const int b   = j4 >> 10;
    const int j   = j4 & (H_ - 1);
    const int time = (d == 0) ? s : (T_ - 1 - s);
    const int tout = (d == 0) ? (T_ - 1 - s) : s;

    const __half* gx = g_gx16 + ((size_t)b * T_ + time) * N3;
    const __half* gh = g_gh16 + (size_t)d * B_ * N3 + (size_t)b * N3;

    // previous fp32 h: from init at s=0, else from out written at step s-1
    float4 h;
    if (s == 0) {
        h = *(const float4*)(g_h0 + (size_t)d * B_ * H_ + (size_t)b * H_ + j);
    } else {
        const int tprev = (d == 0) ? (T_ - s) : (s - 1);
        h = *(const float4*)(out + ((size_t)b * T_ + tprev) * (2 * H_) +
                             (size_t)d * H_ + j);
    }
    const size_t hoff = ((size_t)d * 2 + ((s + 1) & 1)) * B_ * H_ + (size_t)b * H_ + j;

    uint2 uxr = *(const uint2*)(gx + j);
    uint2 uxz = *(const uint2*)(gx + H_ + j);
    uint2 uxt = *(const uint2*)(gx + 2 * H_ + j);
    uint2 uhr = *(const uint2*)(gh + j);
    uint2 uhz = *(const uint2*)(gh + H_ + j);
    uint2 uht = *(const uint2*)(gh + 2 * H_ + j);
    float4 bir = *(const float4*)(b_izr + j);
    float4 biz = *(const float4*)(b_izr + H_ + j);
    float4 bhr = *(const float4*)(b_hzr + j);
    float4 bhz = *(const float4*)(b_hzr + H_ + j);
    float4 bti = *(const float4*)(b_it + j);
    float4 bth = *(const float4*)(b_ht + j);

    float2 xr0 = __half22float2(*reinterpret_cast<__half2*>(&uxr.x));
    float2 xr1 = __half22float2(*reinterpret_cast<__half2*>(&uxr.y));
    float2 xz0 = __half22float2(*reinterpret_cast<__half2*>(&uxz.x));
    float2 xz1 = __half22float2(*reinterpret_cast<__half2*>(&uxz.y));
    float2 xt0 = __half22float2(*reinterpret_cast<__half2*>(&uxt.x));
    float2 xt1 = __half22float2(*reinterpret_cast<__half2*>(&uxt.y));
    float2 hr0 = __half22float2(*reinterpret_cast<__half2*>(&uhr.x));
    float2 hr1 = __half22float2(*reinterpret_cast<__half2*>(&uhr.y));
    float2 hz0 = __half22float2(*reinterpret_cast<__half2*>(&uhz.x));
    float2 hz1 = __half22float2(*reinterpret_cast<__half2*>(&uhz.y));
    float2 ht0 = __half22float2(*reinterpret_cast<__half2*>(&uht.x));
    float2 ht1 = __half22float2(*reinterpret_cast<__half2*>(&uht.y));

    float4 nh;
#define GATE(c, GXR, GHR, GXZ, GHZ, GXT, GHT)                               \
    {                                                                       \
        float rg = sigmoidf_(GXR + GHR + bir.c + bhr.c);                    \
        float zg = sigmoidf_(GXZ + GHZ + biz.c + bhz.c);                    \
        float ht = tanhf(GXT + bti.c + rg * (GHT + bth.c));                 \
        nh.c = zg * ht + (1.f - zg) * h.c;                                  \
    }
    GATE(x, xr0.x, hr0.x, xz0.x, hz0.x, xt0.x, ht0.x)
    GATE(y, xr0.y, hr0.y, xz0.y, hz0.y, xt0.y, ht0.y)
    GATE(z, xr1.x, hr1.x, xz1.x, hz1.x, xt1.x, ht1.x)
    GATE(w, xr1.y, hr1.y, xz1.y, hz1.y, xt1.y, ht1.y)
#undef GATE

    __half2 p0 = __floats2half2_rn(nh.x, nh.y);
    __half2 p1 = __floats2half2_rn(nh.z, nh.w);
    uint2 u; u.x = *reinterpret_cast<uint32_t*>(&p0); u.y = *reinterpret_cast<uint32_t*>(&p1);
    *reinterpret_cast<uint2*>(g_h16 + hoff) = u;
    *(float4*)(out + ((size_t)b * T_ + tout) * (2 * H_) + (size_t)d * H_ + j) = nh;
}

// ------------------------------ small kernels ------------------------------
__global__ void cvt16(const float* __restrict__ s, __half* __restrict__ d, int n4)
{
    int i = blockIdx.x * blockDim.x + threadIdx.x;
    if (i < n4) {
        float4 v = reinterpret_cast<const float4*>(s)[i];
        __half2 p0 = __floats2half2_rn(v.x, v.y);
        __half2 p1 = __floats2half2_rn(v.z, v.w);
        uint2 u; u.x = *reinterpret_cast<uint32_t*>(&p0); u.y = *reinterpret_cast<uint32_t*>(&p1);
        reinterpret_cast<uint2*>(d)[i] = u;
    }
}

__global__ void init_h(const float* __restrict__ h0, const float* __restrict__ bih0)
{
    size_t i = (size_t)blockIdx.x * blockDim.x + threadIdx.x;
    if (i < (size_t)B_ * H_) {
        float a = h0[i], b = bih0[i];
        g_h0[i] = a;
        g_h0[(size_t)B_ * H_ + i] = b;
        g_h16[i] = __float2half_rn(a);                       // dir 0, phase 0
        g_h16[(size_t)2 * B_ * H_ + i] = __float2half_rn(b); // dir 1, phase 0
    }
}

// ------------------------------ host side ----------------------------------
extern "C" void kernel_launch(void* const* d_in, const int* in_sizes, int n_in,
                              void* d_out, int out_size)
{
    const float* x     = (const float*)d_in[0];
    const float* h0    = (const float*)d_in[1];
    const float* bih0  = (const float*)d_in[2];
    const float* W_izr = (const float*)d_in[3];
    const float* b_izr = (const float*)d_in[4];
    const float* W_hzr = (const float*)d_in[5];
    const float* b_hzr = (const float*)d_in[6];
    const float* W_it  = (const float*)d_in[7];
    const float* b_it  = (const float*)d_in[8];
    const float* W_ht  = (const float*)d_in[9];
    const float* b_ht  = (const float*)d_in[10];
    float* out = (float*)d_out;
    (void)in_sizes; (void)n_in; (void)out_size;

    void *p_x16 = nullptr, *p_wx = nullptr, *p_wh = nullptr;
    cudaGetSymbolAddress(&p_x16, g_x16);
    cudaGetSymbolAddress(&p_wx, g_wx16);
    cudaGetSymbolAddress(&p_wh, g_wh16);

    cudaFuncSetAttribute(gemm_f16, cudaFuncAttributeMaxDynamicSharedMemorySize, SMEM_BYTES);

    // fork a second stream into the captured graph (dir1 chain lives there)
    cudaStream_t st2;
    cudaStreamCreateWithFlags(&st2, cudaStreamNonBlocking);
    cudaEvent_t evFork, evPrep2, evGx, evJoin;
    cudaEventCreateWithFlags(&evFork,  cudaEventDisableTiming);
    cudaEventCreateWithFlags(&evPrep2, cudaEventDisableTiming);
    cudaEventCreateWithFlags(&evGx,    cudaEventDisableTiming);
    cudaEventCreateWithFlags(&evJoin,  cudaEventDisableTiming);

    cudaEventRecord(evFork, 0);
    cudaStreamWaitEvent(st2, evFork, 0);

    // prep split across streams
    const int WN4 = 2 * H_ * K_ / 4, WN4b = H_ * K_ / 4, XN4 = B_ * T_ * K_ / 4;
    cvt16<<<(WN4 + 255) / 256, 256>>>(W_izr, (__half*)p_wx, WN4);
    cvt16<<<(WN4b + 255) / 256, 256>>>(W_it, (__half*)p_wx + (size_t)2 * H_ * K_, WN4b);
    cvt16<<<(XN4 + 255) / 256, 256>>>(x, (__half*)p_x16, XN4);
    cvt16<<<(WN4 + 255) / 256, 256, 0, st2>>>(W_hzr, (__half*)p_wh, WN4);
    cvt16<<<(WN4b + 255) / 256, 256, 0, st2>>>(W_ht, (__half*)p_wh + (size_t)2 * H_ * K_, WN4b);
    init_h<<<(B_ * H_ + 255) / 256, 256, 0, st2>>>(h0, bih0);
    cudaEventRecord(evPrep2, st2);

    // Gx = X @ [W_izr; W_it]^T over all (b, t)   (stream 0)
    gemm_f16<<<dim3(N3 / BN, (B_ * T_) / BM), 128, SMEM_BYTES>>>(0, 0, 0);
    cudaEventRecord(evGx, 0);

    // stream 0's chain needs wh16/h16 (prep on st2); st2's chain needs Gx
    cudaStreamWaitEvent(0, evPrep2, 0);
    cudaStreamWaitEvent(st2, evGx, 0);

    const int GATE_BLKS = (B_ * H_) / (256 * 4);
    for (int s = 0; s < T_; ++s) {
        gemm_f16<<<dim3(N3 / BN, B_ / BM), 128, SMEM_BYTES>>>(0, s & 1, 1);
        gemm_f16<<<dim3(N3 / BN, B_ / BM), 128, SMEM_BYTES, st2>>>(1, s & 1, 1);
        gate_kernel<<<GATE_BLKS, 256>>>(b_izr, b_hzr, b_it, b_ht, out, 0, s);
        gate_kernel<<<GATE_BLKS, 256, 0, st2>>>(b_izr, b_hzr, b_it, b_ht, out, 1, s);
    }

    // join st2 back into the captured stream
    cudaEventRecord(evJoin, st2);
    cudaStreamWaitEvent(0, evJoin, 0);
}